// round 3
// baseline (speedup 1.0000x reference)
#include <cuda_runtime.h>
#include <cuda_bf16.h>

// Word2Vec negative-sampling loss:
//   loss = -sum_b [ log_sigmoid(dot(i_b, o_b)) + log_sigmoid(-sum_k dot(n_{b,k}, i_b)) ]
// Inputs (metadata order): iemb_w [V,128] f32, oemb_w [V,128] f32,
//                          iwords [B] i32, owords [B] i32, negwords [B,10] i32
// Output: scalar f32.
//
// Single fused kernel: one warp per batch element (12 coalesced 512B row
// gathers, front-batched for MLP), per-block partial, fenced last-block
// final reduction. Deterministic: the float sum runs in a fixed order in
// exactly one block; atomics touch only an int ticket counter.

#define EMB 128
#define NEGS 10
#define WARPS_PER_BLOCK 8
#define THREADS (WARPS_PER_BLOCK * 32)
#define MAX_BLOCKS 4096
#define BATCH_MAX (MAX_BLOCKS * WARPS_PER_BLOCK)

__device__ float g_partials[MAX_BLOCKS];
__device__ unsigned int g_ticket = 0;   // reset to 0 by the last block each call

__device__ __forceinline__ float logsig(float x) {
    // log(sigmoid(x)) = min(x,0) - log1p(exp(-|x|))   (numerically stable)
    return fminf(x, 0.0f) - log1pf(__expf(-fabsf(x)));
}

__device__ __forceinline__ float warp_sum(float v) {
    #pragma unroll
    for (int off = 16; off > 0; off >>= 1)
        v += __shfl_xor_sync(0xffffffffu, v, off);
    return v;
}

__global__ __launch_bounds__(THREADS)
void w2v_loss_kernel(const float* __restrict__ iemb_w,
                     const float* __restrict__ oemb_w,
                     const int*   __restrict__ iwords,
                     const int*   __restrict__ owords,
                     const int*   __restrict__ negwords,
                     float*       __restrict__ out,
                     int batch, int nblocks)
{
    const int warp_in_block = threadIdx.x >> 5;
    const int lane          = threadIdx.x & 31;
    const int b             = blockIdx.x * WARPS_PER_BLOCK + warp_in_block;

    float loss = 0.0f;

    if (b < batch) {
        // Each lane owns 4 consecutive floats of the 128-wide row (one float4
        // => every row read is one coalesced 512B transaction per warp).
        const int iw = iwords[b];
        const float4 iv = *reinterpret_cast<const float4*>(iemb_w + (size_t)iw * EMB + lane * 4);

        const int ow = owords[b];
        const float4 ov = *reinterpret_cast<const float4*>(oemb_w + (size_t)ow * EMB + lane * 4);
        float pos_part = iv.x * ov.x + iv.y * ov.y + iv.z * ov.z + iv.w * ov.w;

        // 10 independent negative-row loads issued up front for max MLP.
        const int* __restrict__ nw = negwords + (size_t)b * NEGS;
        float4 nv[NEGS];
        #pragma unroll
        for (int k = 0; k < NEGS; k++) {
            const int idx = nw[k];
            nv[k] = *reinterpret_cast<const float4*>(oemb_w + (size_t)idx * EMB + lane * 4);
        }
        float neg_part = 0.0f;
        #pragma unroll
        for (int k = 0; k < NEGS; k++) {
            neg_part += iv.x * nv[k].x + iv.y * nv[k].y + iv.z * nv[k].z + iv.w * nv[k].w;
        }

        const float pos_score = warp_sum(pos_part);
        const float neg_score = warp_sum(neg_part);

        if (lane == 0) {
            loss = -(logsig(pos_score) + logsig(-neg_score));
        }
    }

    // Block partial: fixed tree over the 8 warp results (deterministic).
    __shared__ float s_warp[WARPS_PER_BLOCK];
    __shared__ bool  s_is_last;
    if (lane == 0) s_warp[warp_in_block] = loss;
    __syncthreads();

    if (threadIdx.x == 0) {
        float acc = 0.0f;
        #pragma unroll
        for (int w = 0; w < WARPS_PER_BLOCK; w++) acc += s_warp[w];
        g_partials[blockIdx.x] = acc;
        // Make the partial globally visible before taking a ticket.
        __threadfence();
        unsigned int t = atomicAdd(&g_ticket, 1u);
        s_is_last = (t == (unsigned int)(nblocks - 1));
    }
    __syncthreads();

    // Exactly one block performs the final sum, in a fixed order -> deterministic.
    if (s_is_last) {
        __shared__ float s_red[THREADS];
        float v = 0.0f;
        for (int i = threadIdx.x; i < nblocks; i += THREADS) v += g_partials[i];
        s_red[threadIdx.x] = v;
        __syncthreads();
        #pragma unroll
        for (int off = THREADS / 2; off > 0; off >>= 1) {
            if (threadIdx.x < off) s_red[threadIdx.x] += s_red[threadIdx.x + off];
            __syncthreads();
        }
        if (threadIdx.x == 0) {
            out[0] = s_red[0];
            g_ticket = 0;   // reset for next graph replay
        }
    }
}

extern "C" void kernel_launch(void* const* d_in, const int* in_sizes, int n_in,
                              void* d_out, int out_size)
{
    const float* iemb_w   = (const float*)d_in[0];
    const float* oemb_w   = (const float*)d_in[1];
    const int*   iwords   = (const int*)d_in[2];
    const int*   owords   = (const int*)d_in[3];
    const int*   negwords = (const int*)d_in[4];
    float*       out      = (float*)d_out;

    int batch = in_sizes[2];
    if (batch > BATCH_MAX) batch = BATCH_MAX;   // scratch-capacity guard (B=16384 fits)
    const int nblocks = (batch + WARPS_PER_BLOCK - 1) / WARPS_PER_BLOCK;

    w2v_loss_kernel<<<nblocks, THREADS>>>(iemb_w, oemb_w, iwords, owords,
                                          negwords, out, batch, nblocks);
}

// round 6
// speedup vs baseline: 1.0110x; 1.0110x over previous
#include <cuda_runtime.h>
#include <cuda_bf16.h>

// Word2Vec negative-sampling loss:
//   loss = -sum_b [ log_sigmoid(dot(i_b, o_b)) + log_sigmoid(-sum_k dot(n_{b,k}, i_b)) ]
// Inputs (metadata order): iemb_w [V,128] f32, oemb_w [V,128] f32,
//                          iwords [B] i32, owords [B] i32, negwords [B,10] i32
// Output: scalar f32.
//
// R5 fix: `ld.global.nc.L2::evict_last` is NOT legal PTX (eviction-priority
// qualifiers are L1-scoped). L2 policy now goes through
// createpolicy.fractional.L2::evict_last.b64 + ld...L2::cache_hint.
// The R3-derived experiment is otherwise unchanged:
//  - 12 row-gathers issued via ordered asm volatile loads => guaranteed MLP=12
//    per warp (R3's regs=32 showed ptxas had interleaved them, MLP~6).
//  - Table lines get L2 evict-last stickiness (102 MB tables vs 126 MB L2).

#define EMB 128
#define NEGS 10
#define WARPS_PER_BLOCK 8
#define THREADS (WARPS_PER_BLOCK * 32)
#define MAX_BLOCKS 4096
#define BATCH_MAX (MAX_BLOCKS * WARPS_PER_BLOCK)

__device__ float g_partials[MAX_BLOCKS];
__device__ unsigned int g_ticket = 0;   // reset to 0 by the last block each call

__device__ __forceinline__ float logsig(float x) {
    // log(sigmoid(x)) = min(x,0) - log1p(exp(-|x|))   (numerically stable)
    return fminf(x, 0.0f) - log1pf(__expf(-fabsf(x)));
}

__device__ __forceinline__ float warp_sum(float v) {
    #pragma unroll
    for (int off = 16; off > 0; off >>= 1)
        v += __shfl_xor_sync(0xffffffffu, v, off);
    return v;
}

// L2 evict-last access policy (persisting lines for the embedding tables).
__device__ __forceinline__ unsigned long long make_evict_last_policy() {
    unsigned long long pol;
    asm("createpolicy.fractional.L2::evict_last.b64 %0, 1.0;" : "=l"(pol));
    return pol;
}

// Ordered, L2-sticky 16B gather. asm volatile keeps issue order and forces the
// result to live in registers until consumed -> guaranteed front-batched MLP.
__device__ __forceinline__ float4 ldg_row16(const float* __restrict__ p,
                                            unsigned long long pol) {
    float4 v;
    asm volatile("ld.global.nc.L2::cache_hint.v4.f32 {%0,%1,%2,%3}, [%4], %5;"
                 : "=f"(v.x), "=f"(v.y), "=f"(v.z), "=f"(v.w)
                 : "l"(p), "l"(pol));
    return v;
}

__global__ __launch_bounds__(THREADS)
void w2v_loss_kernel(const float* __restrict__ iemb_w,
                     const float* __restrict__ oemb_w,
                     const int*   __restrict__ iwords,
                     const int*   __restrict__ owords,
                     const int*   __restrict__ negwords,
                     float*       __restrict__ out,
                     int batch, int nblocks)
{
    const int warp_in_block = threadIdx.x >> 5;
    const int lane          = threadIdx.x & 31;
    const int b             = blockIdx.x * WARPS_PER_BLOCK + warp_in_block;

    float loss = 0.0f;

    if (b < batch) {
        const int l4 = lane * 4;   // each lane owns 4 consecutive floats of the row
        const unsigned long long pol = make_evict_last_policy();

        // Resolve all 12 indices first (small coalesced/broadcast loads).
        const int iw = iwords[b];
        const int ow = owords[b];
        const int* __restrict__ nw = negwords + (size_t)b * NEGS;
        int nidx[NEGS];
        #pragma unroll
        for (int k = 0; k < NEGS; k++) nidx[k] = nw[k];

        // Issue ALL 12 row gathers back-to-back (true MLP=12; each is one
        // coalesced 512B warp transaction, L2 evict-last priority).
        const float4 iv = ldg_row16(iemb_w + (size_t)iw * EMB + l4, pol);
        const float4 ov = ldg_row16(oemb_w + (size_t)ow * EMB + l4, pol);
        float4 nv[NEGS];
        #pragma unroll
        for (int k = 0; k < NEGS; k++)
            nv[k] = ldg_row16(oemb_w + (size_t)nidx[k] * EMB + l4, pol);

        float pos_part = iv.x * ov.x + iv.y * ov.y + iv.z * ov.z + iv.w * ov.w;
        float neg_part = 0.0f;
        #pragma unroll
        for (int k = 0; k < NEGS; k++)
            neg_part += iv.x * nv[k].x + iv.y * nv[k].y + iv.z * nv[k].z + iv.w * nv[k].w;

        const float pos_score = warp_sum(pos_part);
        const float neg_score = warp_sum(neg_part);

        if (lane == 0)
            loss = -(logsig(pos_score) + logsig(-neg_score));
    }

    // Block partial: fixed tree over the 8 warp results (deterministic).
    __shared__ float s_warp[WARPS_PER_BLOCK];
    __shared__ bool  s_is_last;
    if (lane == 0) s_warp[warp_in_block] = loss;
    __syncthreads();

    if (threadIdx.x == 0) {
        float acc = 0.0f;
        #pragma unroll
        for (int w = 0; w < WARPS_PER_BLOCK; w++) acc += s_warp[w];
        g_partials[blockIdx.x] = acc;
        __threadfence();
        unsigned int t = atomicAdd(&g_ticket, 1u);
        s_is_last = (t == (unsigned int)(nblocks - 1));
    }
    __syncthreads();

    // Exactly one block performs the final sum, in a fixed order -> deterministic.
    if (s_is_last) {
        __shared__ float s_red[THREADS];
        float v = 0.0f;
        for (int i = threadIdx.x; i < nblocks; i += THREADS) v += g_partials[i];
        s_red[threadIdx.x] = v;
        __syncthreads();
        #pragma unroll
        for (int off = THREADS / 2; off > 0; off >>= 1) {
            if (threadIdx.x < off) s_red[threadIdx.x] += s_red[threadIdx.x + off];
            __syncthreads();
        }
        if (threadIdx.x == 0) {
            out[0] = s_red[0];
            g_ticket = 0;   // reset for next graph replay
        }
    }
}

extern "C" void kernel_launch(void* const* d_in, const int* in_sizes, int n_in,
                              void* d_out, int out_size)
{
    const float* iemb_w   = (const float*)d_in[0];
    const float* oemb_w   = (const float*)d_in[1];
    const int*   iwords   = (const int*)d_in[2];
    const int*   owords   = (const int*)d_in[3];
    const int*   negwords = (const int*)d_in[4];
    float*       out      = (float*)d_out;

    int batch = in_sizes[2];
    if (batch > BATCH_MAX) batch = BATCH_MAX;   // scratch-capacity guard (B=16384 fits)
    const int nblocks = (batch + WARPS_PER_BLOCK - 1) / WARPS_PER_BLOCK;

    w2v_loss_kernel<<<nblocks, THREADS>>>(iemb_w, oemb_w, iwords, owords,
                                          negwords, out, batch, nblocks);
}